// round 15
// baseline (speedup 1.0000x reference)
#include <cuda_runtime.h>
#include <cuda_fp16.h>
#include <math.h>
#include <stdint.h>

#define NHEADS 8
#define DMODEL 1024
#define DHEAD  128
#define KFDIM  3072
#define NSENT  2048
#define NKNOW  8192

// Scratch (no cudaMalloc allowed).
__device__ __half g_snth[NSENT * DMODEL];               // 4 MB  sentences fp16
__device__ __half g_wsh[NHEADS * DMODEL * DHEAD];       // 2 MB  w_s fp16
__device__ __half g_Sh[NHEADS * NSENT * DHEAD];         // 4 MB  S fp16
__device__ __half g_Kh[NHEADS * NKNOW * DHEAD];         // 16 MB K fp16
__device__ __half g_wkh[NHEADS * KFDIM * DHEAD];        // 6 MB  w_k fp16
__device__ float  g_colsum[NHEADS * NKNOW];             // 256 KB
__device__ __half g_Ah[(size_t)NHEADS * NSENT * NKNOW]; // 268 MB e fp16
__device__ __half g_An[(size_t)NHEADS * NSENT * NKNOW]; // 268 MB normalized fp16
__device__ __half g_Bh[(size_t)NKNOW * KFDIM];          // 50 MB knowledge fp16

// ===========================================================================
// helpers
// ===========================================================================
__device__ __forceinline__ void mma_f16(float* d, const uint32_t* a, const uint32_t* b) {
    asm volatile(
        "mma.sync.aligned.m16n8k16.row.col.f32.f16.f16.f32 "
        "{%0,%1,%2,%3}, {%4,%5,%6,%7}, {%8,%9}, {%0,%1,%2,%3};"
        : "+f"(d[0]), "+f"(d[1]), "+f"(d[2]), "+f"(d[3])
        : "r"(a[0]), "r"(a[1]), "r"(a[2]), "r"(a[3]), "r"(b[0]), "r"(b[1]));
}
__device__ __forceinline__ void cp_async16(uint32_t dst, const void* src) {
    asm volatile("cp.async.cg.shared.global [%0], [%1], 16;" :: "r"(dst), "l"(src));
}
__device__ __forceinline__ void ldsm_x4(uint32_t* r, uint32_t addr) {
    asm volatile("ldmatrix.sync.aligned.m8n8.x4.shared.b16 {%0,%1,%2,%3}, [%4];"
                 : "=r"(r[0]), "=r"(r[1]), "=r"(r[2]), "=r"(r[3]) : "r"(addr));
}
__device__ __forceinline__ void ldsm_x4_t(uint32_t* r, uint32_t addr) {
    asm volatile("ldmatrix.sync.aligned.m8n8.x4.trans.shared.b16 {%0,%1,%2,%3}, [%4];"
                 : "=r"(r[0]), "=r"(r[1]), "=r"(r[2]), "=r"(r[3]) : "r"(addr));
}

// fp32 -> fp16 (rn)
__global__ __launch_bounds__(256)
void cvt_f16_kernel(const float* __restrict__ in, __half* __restrict__ out)
{
    size_t i = ((size_t)blockIdx.x * 256 + threadIdx.x) * 4;
    float4 v = *(const float4*)(in + i);
    *(__half2*)(out + i)     = __floats2half2_rn(v.x, v.y);
    *(__half2*)(out + i + 2) = __floats2half2_rn(v.z, v.w);
}

// ===========================================================================
// Generic per-head projection on fp16 tensor cores
// ===========================================================================
#define KP_STG 4
#define KPA_STR 40
#define KPB_STR 136
#define KPA_H (128 * KPA_STR)
#define KPB_H (32 * KPB_STR)
#define KPSMEM (KP_STG * (KPA_H + KPB_H) * 2)   // 75776 B

__global__ void __launch_bounds__(256, 2)
proj_f16_kernel(const __half* __restrict__ A, const __half* __restrict__ W,
                const float* __restrict__ bias, __half* __restrict__ out,
                int Kdim, int Mtot)
{
    extern __shared__ __half kps[];
    const uint32_t sA = (uint32_t)__cvta_generic_to_shared(kps);
    const uint32_t sB = sA + KP_STG * KPA_H * 2;

    const int tid  = threadIdx.x;
    const int lane = tid & 31;
    const int wid  = tid >> 5;
    const int wm   = wid >> 2;
    const int wn   = wid & 3;
    const int z    = blockIdx.z;
    const int m0   = blockIdx.y * 128;

    const __half* Ap = A + (size_t)m0 * Kdim;
    const __half* Bp = W + (size_t)z * Kdim * DHEAD;

    const int a_r = tid >> 1;
    const int a_c = (tid & 1) << 4;
    const int b_r = tid >> 3;
    const int b_c = (tid & 7) << 4;

    float acc[4][4][4];
#pragma unroll
    for (int mt = 0; mt < 4; mt++)
#pragma unroll
        for (int nt = 0; nt < 4; nt++)
#pragma unroll
            for (int r = 0; r < 4; r++) acc[mt][nt][r] = 0.f;

    const int NT = Kdim / 32;

    auto issue = [&](int kt, int s) {
#pragma unroll
        for (int i = 0; i < 2; i++)
            cp_async16(sA + (uint32_t)(s * KPA_H + a_r * KPA_STR + a_c + 8 * i) * 2,
                       Ap + (size_t)a_r * Kdim + kt * 32 + a_c + 8 * i);
#pragma unroll
        for (int i = 0; i < 2; i++)
            cp_async16(sB + (uint32_t)(s * KPB_H + b_r * KPB_STR + b_c + 8 * i) * 2,
                       Bp + (size_t)(kt * 32 + b_r) * DHEAD + b_c + 8 * i);
        asm volatile("cp.async.commit_group;" ::: "memory");
    };

    issue(0, 0); issue(1, 1); issue(2, 2);

    int scur = 0;
    for (int kt = 0; kt < NT; kt++) {
        if (kt < NT - 2)       asm volatile("cp.async.wait_group 2;" ::: "memory");
        else if (kt == NT - 2) asm volatile("cp.async.wait_group 1;" ::: "memory");
        else                   asm volatile("cp.async.wait_group 0;" ::: "memory");
        __syncthreads();

        if (kt + 3 < NT) {
            int snx = scur + 3; if (snx >= KP_STG) snx -= KP_STG;
            issue(kt + 3, snx);
        }

        const uint32_t aB = sA + (uint32_t)(scur * KPA_H) * 2;
        const uint32_t bB = sB + (uint32_t)(scur * KPB_H) * 2;

#pragma unroll
        for (int ks = 0; ks < 2; ks++) {
            uint32_t bf[4][2];
#pragma unroll
            for (int ntp = 0; ntp < 2; ntp++) {
                uint32_t r[4];
                uint32_t addr = bB + (uint32_t)(((ks * 16 + (lane & 15)) * KPB_STR
                               + wn * 32 + ntp * 16 + ((lane >> 4) << 3)) * 2);
                ldsm_x4_t(r, addr);
                bf[2 * ntp][0]     = r[0];
                bf[2 * ntp][1]     = r[1];
                bf[2 * ntp + 1][0] = r[2];
                bf[2 * ntp + 1][1] = r[3];
            }
#pragma unroll
            for (int mt = 0; mt < 4; mt++) {
                uint32_t af[4];
                uint32_t addr = aB + (uint32_t)(((wm * 64 + mt * 16 + (lane & 15)) * KPA_STR
                               + ks * 16 + ((lane >> 4) << 3)) * 2);
                ldsm_x4(af, addr);
#pragma unroll
                for (int nt = 0; nt < 4; nt++)
                    mma_f16(acc[mt][nt], af, bf[nt]);
            }
        }
        scur++; if (scur >= KP_STG) scur -= KP_STG;
        __syncthreads();
    }

    __half* Op = out + (size_t)z * Mtot * DHEAD;
#pragma unroll
    for (int mt = 0; mt < 4; mt++) {
        const int r = m0 + wm * 64 + mt * 16 + (lane >> 2);
#pragma unroll
        for (int nt = 0; nt < 4; nt++) {
            const int c = wn * 32 + nt * 8 + ((lane & 3) << 1);
            float b0 = bias[z * DHEAD + c], b1 = bias[z * DHEAD + c + 1];
            *(__half2*)(Op + (size_t)r * DHEAD + c) =
                __floats2half2_rn(acc[mt][nt][0] + b0, acc[mt][nt][1] + b1);
            *(__half2*)(Op + (size_t)(r + 8) * DHEAD + c) =
                __floats2half2_rn(acc[mt][nt][2] + b0, acc[mt][nt][3] + b1);
        }
    }
}

// ===========================================================================
// Scores (per-head z param), CTA tile 128m x 256n, 512 thr (16 warps 4x4)
// ===========================================================================
#define SC_STR 136
#define SC_SMEM ((128 + 256) * SC_STR * 2)   // 104448 B dynamic

__global__ void __launch_bounds__(512, 1)
scores_f16_kernel(float scale, int z)
{
    extern __shared__ __half scs[];
    const uint32_t sA = (uint32_t)__cvta_generic_to_shared(scs);
    const uint32_t sB = sA + 128 * SC_STR * 2;
    __shared__ float red[32][256];

    const int tid  = threadIdx.x;
    const int lane = tid & 31;
    const int wid  = tid >> 5;
    const int wm   = wid >> 2;
    const int wn   = wid & 3;
    const int m0   = blockIdx.y * 128;
    const int n0   = blockIdx.x * 256;

    const __half* Ap = g_Sh + (size_t)z * NSENT * DHEAD + (size_t)m0 * DHEAD;
    const __half* Bp = g_Kh + (size_t)z * NKNOW * DHEAD + (size_t)n0 * DHEAD;

    {
        const int ra  = tid >> 2;
        const int ca  = (tid & 3) << 5;
#pragma unroll
        for (int i = 0; i < 4; i++)
            cp_async16(sA + (uint32_t)(ra * SC_STR + ca + 8 * i) * 2,
                       Ap + (size_t)ra * DHEAD + ca + 8 * i);
        const int rb  = tid >> 1;
        const int cb  = (tid & 1) << 6;
#pragma unroll
        for (int i = 0; i < 8; i++)
            cp_async16(sB + (uint32_t)(rb * SC_STR + cb + 8 * i) * 2,
                       Bp + (size_t)rb * DHEAD + cb + 8 * i);
        asm volatile("cp.async.commit_group;" ::: "memory");
        asm volatile("cp.async.wait_group 0;" ::: "memory");
        __syncthreads();
    }

    float acc[2][8][4];
#pragma unroll
    for (int mt = 0; mt < 2; mt++)
#pragma unroll
        for (int nt = 0; nt < 8; nt++)
#pragma unroll
            for (int r = 0; r < 4; r++) acc[mt][nt][r] = 0.f;

#pragma unroll
    for (int ks = 0; ks < 8; ks++) {
        uint32_t bf[8][2];
#pragma unroll
        for (int ntp = 0; ntp < 4; ntp++) {
            uint32_t r[4];
            uint32_t addr = sB + (uint32_t)(((wn * 64 + ntp * 16 + (lane & 15)) * SC_STR
                           + ks * 16 + ((lane >> 4) << 3)) * 2);
            ldsm_x4(r, addr);
            bf[2 * ntp][0]     = r[0];
            bf[2 * ntp][1]     = r[2];
            bf[2 * ntp + 1][0] = r[1];
            bf[2 * ntp + 1][1] = r[3];
        }
#pragma unroll
        for (int mt = 0; mt < 2; mt++) {
            uint32_t af[4];
            uint32_t addr = sA + (uint32_t)(((wm * 32 + mt * 16 + (lane & 15)) * SC_STR
                           + ks * 16 + ((lane >> 4) << 3)) * 2);
            ldsm_x4(af, addr);
#pragma unroll
            for (int nt = 0; nt < 8; nt++)
                mma_f16(acc[mt][nt], af, bf[nt]);
        }
    }

    float cp[16];
#pragma unroll
    for (int j = 0; j < 16; j++) cp[j] = 0.f;
    __half* Ep = g_Ah + (size_t)z * NSENT * NKNOW;
#pragma unroll
    for (int mt = 0; mt < 2; mt++) {
        const int r = m0 + wm * 32 + mt * 16 + (lane >> 2);
#pragma unroll
        for (int nt = 0; nt < 8; nt++) {
            const int c = n0 + wn * 64 + nt * 8 + ((lane & 3) << 1);
            float e0 = __expf(acc[mt][nt][0] * scale);
            float e1 = __expf(acc[mt][nt][1] * scale);
            float e2 = __expf(acc[mt][nt][2] * scale);
            float e3 = __expf(acc[mt][nt][3] * scale);
            *(__half2*)(Ep + (size_t)r * NKNOW + c)       = __floats2half2_rn(e0, e1);
            *(__half2*)(Ep + (size_t)(r + 8) * NKNOW + c) = __floats2half2_rn(e2, e3);
            cp[nt * 2]     += e0 + e2;
            cp[nt * 2 + 1] += e1 + e3;
        }
    }
    const int rr = wm * 8 + (lane >> 2);
#pragma unroll
    for (int nt = 0; nt < 8; nt++) {
        red[rr][wn * 64 + nt * 8 + ((lane & 3) << 1)]     = cp[nt * 2];
        red[rr][wn * 64 + nt * 8 + ((lane & 3) << 1) + 1] = cp[nt * 2 + 1];
    }
    __syncthreads();
    if (tid < 256) {
        float s = 0.f;
#pragma unroll
        for (int r = 0; r < 32; r++) s += red[r][tid];
        atomicAdd(&g_colsum[(size_t)z * NKNOW + n0 + tid], s);
    }
}

// ===========================================================================
// normalize_a (per-head): g_An = f16( e * 1/colsum )
// ===========================================================================
__global__ __launch_bounds__(256)
void normalize_a_kernel(int h)
{
    const int m = (blockIdx.x * 256 + threadIdx.x) * 2;
    const int n0 = blockIdx.y * 64;
    float2 cs = *(const float2*)&g_colsum[(size_t)h * NKNOW + m];
    const float iv0 = 1.f / cs.x, iv1 = 1.f / cs.y;
    const size_t base = (size_t)h * NSENT * NKNOW + (size_t)n0 * NKNOW + m;
    const __half* pe = g_Ah + base;
    __half*       pn = g_An + base;
#pragma unroll 4
    for (int nn = 0; nn < 64; nn++) {
        size_t idx = (size_t)nn * NKNOW;
        __half2 e = *(const __half2*)(pe + idx);
        *(__half2*)(pn + idx) = __floats2half2_rn(__half2float(__low2half(e))  * iv0,
                                                  __half2float(__high2half(e)) * iv1);
    }
}

// ===========================================================================
// normalize_b (per-head): attn fp32 = e * 1/colsum
// ===========================================================================
__global__ __launch_bounds__(256)
void normalize_b_kernel(float* __restrict__ attn, int h)
{
    const int m = (blockIdx.x * 256 + threadIdx.x) * 2;
    const int n0 = blockIdx.y * 64;
    float2 cs = *(const float2*)&g_colsum[(size_t)h * NKNOW + m];
    const float iv0 = 1.f / cs.x, iv1 = 1.f / cs.y;
    const size_t base = (size_t)h * NSENT * NKNOW + (size_t)n0 * NKNOW + m;
    const __half* pe = g_Ah + base;
    float*        p  = attn + base;
#pragma unroll 4
    for (int nn = 0; nn < 64; nn++) {
        size_t idx = (size_t)nn * NKNOW;
        __half2 e = *(const __half2*)(pe + idx);
        *(float2*)(p + idx) = make_float2(__half2float(__low2half(e))  * iv0,
                                          __half2float(__high2half(e)) * iv1);
    }
}

// ===========================================================================
// fused (per-head z param) — R9 config: CTA 128x256xK64, 512 thr, 3-stage
// ===========================================================================
#define FBM 128
#define FBN 256
#define FBK 64
#define FSTG 3
#define SA_STR 72
#define SB_STR 264
#define SA_H (FBM * SA_STR)
#define SB_H (FBK * SB_STR)
#define FSMEM (FSTG * (SA_H + SB_H) * 2)    // 156672 B

__global__ void __launch_bounds__(512, 1)
fused_mma_f16(float* __restrict__ C, int z)
{
    extern __shared__ __half smh[];
    const uint32_t sA_u32 = (uint32_t)__cvta_generic_to_shared(smh);
    const uint32_t sB_u32 = sA_u32 + FSTG * SA_H * 2;

    const int tid  = threadIdx.x;
    const int lane = tid & 31;
    const int wid  = tid >> 5;
    const int wm   = wid & 3;
    const int wn   = wid >> 2;
    const int m0   = blockIdx.y * FBM;
    const int n0   = blockIdx.x * FBN;

    const __half* Ap = g_An + (size_t)z * NSENT * NKNOW + (size_t)m0 * NKNOW;
    const __half* Bp = g_Bh + n0;

    const int a_row  = tid >> 2;
    const int a_ch   = (tid & 3) << 3;
    const int b_row0 = tid >> 5;
    const int b_ch0  = (tid & 31) << 3;

    float acc[2][8][4];
#pragma unroll
    for (int mt = 0; mt < 2; mt++)
#pragma unroll
        for (int nt = 0; nt < 8; nt++)
#pragma unroll
            for (int r = 0; r < 4; r++) acc[mt][nt][r] = 0.f;

    const int NT = NKNOW / FBK;             // 128

    auto issue = [&](int kt, int s) {
        const __half* abase = Ap + (size_t)kt * FBK;
#pragma unroll
        for (int i = 0; i < 2; i++)
            cp_async16(sA_u32 + (uint32_t)(s * SA_H + a_row * SA_STR + a_ch + 32 * i) * 2,
                       abase + (size_t)a_row * NKNOW + a_ch + 32 * i);
        const __half* bbase = Bp + (size_t)(kt * FBK) * KFDIM;
#pragma unroll
        for (int p = 0; p < 4; p++) {
            int row = b_row0 + p * 16;
            cp_async16(sB_u32 + (uint32_t)(s * SB_H + row * SB_STR + b_ch0) * 2,
                       bbase + (size_t)row * KFDIM + b_ch0);
        }
        asm volatile("cp.async.commit_group;" ::: "memory");
    };

    issue(0, 0); issue(1, 1);

    int scur = 0;
    for (int kt = 0; kt < NT; kt++) {
        if (kt + 1 < NT) asm volatile("cp.async.wait_group 1;" ::: "memory");
        else             asm volatile("cp.async.wait_group 0;" ::: "memory");
        __syncthreads();

        if (kt + 2 < NT) {
            int snx = scur + 2; if (snx >= FSTG) snx -= FSTG;
            issue(kt + 2, snx);
        }

        const uint32_t aBase = sA_u32 + (uint32_t)(scur * SA_H) * 2;
        const uint32_t bBase = sB_u32 + (uint32_t)(scur * SB_H) * 2;

#pragma unroll
        for (int ks = 0; ks < 4; ks++) {
            uint32_t bf[8][2];
#pragma unroll
            for (int ntp = 0; ntp < 4; ntp++) {
                uint32_t r[4];
                uint32_t addr = bBase + (uint32_t)(((ks * 16 + (lane & 15)) * SB_STR
                               + wn * 64 + ntp * 16 + ((lane >> 4) << 3)) * 2);
                ldsm_x4_t(r, addr);
                bf[2 * ntp][0]     = r[0];
                bf[2 * ntp][1]     = r[1];
                bf[2 * ntp + 1][0] = r[2];
                bf[2 * ntp + 1][1] = r[3];
            }
#pragma unroll
            for (int mt = 0; mt < 2; mt++) {
                uint32_t af[4];
                uint32_t addr = aBase + (uint32_t)(((wm * 32 + mt * 16 + (lane & 15)) * SA_STR
                               + ks * 16 + ((lane >> 4) << 3)) * 2);
                ldsm_x4(af, addr);
#pragma unroll
                for (int nt = 0; nt < 8; nt++)
                    mma_f16(acc[mt][nt], af, bf[nt]);
            }
        }
        scur++; if (scur >= FSTG) scur -= FSTG;
    }

    const int ldc = NHEADS * KFDIM;
#pragma unroll
    for (int mt = 0; mt < 2; mt++) {
        const int r = m0 + wm * 32 + mt * 16 + (lane >> 2);
#pragma unroll
        for (int nt = 0; nt < 8; nt++) {
            const int c = z * KFDIM + n0 + wn * 64 + nt * 8 + ((lane & 3) << 1);
            *(float2*)(C + (size_t)r * ldc + c)       = make_float2(acc[mt][nt][0], acc[mt][nt][1]);
            *(float2*)(C + (size_t)(r + 8) * ldc + c) = make_float2(acc[mt][nt][2], acc[mt][nt][3]);
        }
    }
}

// ===========================================================================
// Host side — per-head pipelined scores -> norm_a -> fused across streams
// ===========================================================================
extern "C" void kernel_launch(void* const* d_in, const int* in_sizes, int n_in,
                              void* d_out, int out_size)
{
    const float* sentences = (const float*)d_in[0];
    const float* knowledge = (const float*)d_in[1];
    const float* w_s       = (const float*)d_in[2];
    const float* b_s       = (const float*)d_in[3];
    const float* w_k       = (const float*)d_in[4];
    const float* b_k       = (const float*)d_in[5];

    float* attn  = (float*)d_out;
    float* fused = (float*)d_out + (size_t)NHEADS * NSENT * NKNOW;

    float* csum = nullptr;
    __half *snth = nullptr, *wsh = nullptr, *Sh = nullptr, *Kh = nullptr,
           *wkh = nullptr, *Bh = nullptr;
    cudaGetSymbolAddress((void**)&csum, g_colsum);
    cudaGetSymbolAddress((void**)&snth, g_snth);
    cudaGetSymbolAddress((void**)&wsh,  g_wsh);
    cudaGetSymbolAddress((void**)&Sh,   g_Sh);
    cudaGetSymbolAddress((void**)&Kh,   g_Kh);
    cudaGetSymbolAddress((void**)&wkh,  g_wkh);
    cudaGetSymbolAddress((void**)&Bh,   g_Bh);

    static cudaStream_t s2, s3, s4;
    static cudaEvent_t evF0, evS, evSc[NHEADS], evNa[NHEADS], evJF, evJB;
    static bool init_done = false;
    if (!init_done) {
        cudaFuncSetAttribute(proj_f16_kernel,
                             cudaFuncAttributeMaxDynamicSharedMemorySize, KPSMEM);
        cudaFuncSetAttribute(scores_f16_kernel,
                             cudaFuncAttributeMaxDynamicSharedMemorySize, SC_SMEM);
        cudaFuncSetAttribute(fused_mma_f16,
                             cudaFuncAttributeMaxDynamicSharedMemorySize, FSMEM);
        cudaStreamCreateWithFlags(&s2, cudaStreamNonBlocking);
        cudaStreamCreateWithFlags(&s3, cudaStreamNonBlocking);
        cudaStreamCreateWithFlags(&s4, cudaStreamNonBlocking);
        cudaEventCreateWithFlags(&evF0, cudaEventDisableTiming);
        cudaEventCreateWithFlags(&evS,  cudaEventDisableTiming);
        cudaEventCreateWithFlags(&evJF, cudaEventDisableTiming);
        cudaEventCreateWithFlags(&evJB, cudaEventDisableTiming);
        for (int z = 0; z < NHEADS; z++) {
            cudaEventCreateWithFlags(&evSc[z], cudaEventDisableTiming);
            cudaEventCreateWithFlags(&evNa[z], cudaEventDisableTiming);
        }
        init_done = true;
    }

    // 0) zero colsums; fork front-end
    cudaMemsetAsync(csum, 0, (size_t)NHEADS * NKNOW * sizeof(float));
    cudaEventRecord(evF0, 0);
    cudaStreamWaitEvent(s2, evF0, 0);

    // s2: sentences chain (cvt -> cvt -> sproj)
    cvt_f16_kernel<<<((size_t)NSENT * DMODEL) / 1024, 256, 0, s2>>>(sentences, snth);
    cvt_f16_kernel<<<((size_t)NHEADS * DMODEL * DHEAD) / 1024, 256, 0, s2>>>(w_s, wsh);
    {
        dim3 grid(1, NSENT / 128, NHEADS);
        proj_f16_kernel<<<grid, 256, KPSMEM, s2>>>(snth, wsh, b_s, Sh, DMODEL, NSENT);
    }
    cudaEventRecord(evS, s2);

    // main: knowledge chain (cvt -> cvt -> kproj)
    cvt_f16_kernel<<<((size_t)NKNOW * KFDIM) / 1024, 256>>>(knowledge, Bh);
    cvt_f16_kernel<<<((size_t)NHEADS * KFDIM * DHEAD) / 1024, 256>>>(w_k, wkh);
    {
        dim3 grid(1, NKNOW / 128, NHEADS);
        proj_f16_kernel<<<grid, 256, KPSMEM>>>(Bh, wkh, b_k, Kh, KFDIM, NKNOW);
    }
    cudaStreamWaitEvent((cudaStream_t)0, evS, 0);   // scores needs Sh + Kh

    // per-head pipeline: scores(z) [main] -> norm_a(z) [s2] -> fused(z) [s3];
    //                    norm_b(z) [s4] off critical path
    const dim3 gridSc(NKNOW / 256, NSENT / 128);
    const dim3 gridNm(NKNOW / 512, NSENT / 64);
    const dim3 gridFu(KFDIM / FBN, NSENT / FBM);
    for (int z = 0; z < NHEADS; z++) {
        scores_f16_kernel<<<gridSc, 512, SC_SMEM>>>(0.08838834764831845f, z);
        cudaEventRecord(evSc[z], 0);

        cudaStreamWaitEvent(s2, evSc[z], 0);
        normalize_a_kernel<<<gridNm, 256, 0, s2>>>(z);
        cudaEventRecord(evNa[z], s2);

        cudaStreamWaitEvent(s3, evNa[z], 0);
        fused_mma_f16<<<gridFu, 512, FSMEM, s3>>>(fused, z);

        cudaStreamWaitEvent(s4, evSc[z], 0);
        normalize_b_kernel<<<gridNm, 256, 0, s4>>>(attn, z);
    }
    cudaEventRecord(evJF, s3);
    cudaEventRecord(evJB, s4);
    cudaStreamWaitEvent((cudaStream_t)0, evJF, 0);
    cudaStreamWaitEvent((cudaStream_t)0, evJB, 0);
}

// round 16
// speedup vs baseline: 1.2998x; 1.2998x over previous
#include <cuda_runtime.h>
#include <cuda_fp16.h>
#include <math.h>
#include <stdint.h>

#define NHEADS 8
#define DMODEL 1024
#define DHEAD  128
#define KFDIM  3072
#define NSENT  2048
#define NKNOW  8192

// Scratch (no cudaMalloc allowed).
__device__ __half g_snth[NSENT * DMODEL];               // 4 MB  sentences fp16
__device__ __half g_wsh[NHEADS * DMODEL * DHEAD];       // 2 MB  w_s fp16
__device__ __half g_Sh[NHEADS * NSENT * DHEAD];         // 4 MB  S fp16
__device__ __half g_Kh[NHEADS * NKNOW * DHEAD];         // 16 MB K fp16
__device__ __half g_wkh[NHEADS * KFDIM * DHEAD];        // 6 MB  w_k fp16
__device__ float  g_colsum[NHEADS * NKNOW];             // 256 KB
__device__ __half g_Ah[(size_t)NHEADS * NSENT * NKNOW]; // 268 MB e fp16
__device__ __half g_An[(size_t)NHEADS * NSENT * NKNOW]; // 268 MB normalized fp16
__device__ __half g_Bh[(size_t)NKNOW * KFDIM];          // 50 MB knowledge fp16

// ===========================================================================
// helpers
// ===========================================================================
__device__ __forceinline__ void mma_f16(float* d, const uint32_t* a, const uint32_t* b) {
    asm volatile(
        "mma.sync.aligned.m16n8k16.row.col.f32.f16.f16.f32 "
        "{%0,%1,%2,%3}, {%4,%5,%6,%7}, {%8,%9}, {%0,%1,%2,%3};"
        : "+f"(d[0]), "+f"(d[1]), "+f"(d[2]), "+f"(d[3])
        : "r"(a[0]), "r"(a[1]), "r"(a[2]), "r"(a[3]), "r"(b[0]), "r"(b[1]));
}
__device__ __forceinline__ void cp_async16(uint32_t dst, const void* src) {
    asm volatile("cp.async.cg.shared.global [%0], [%1], 16;" :: "r"(dst), "l"(src));
}
__device__ __forceinline__ void ldsm_x4(uint32_t* r, uint32_t addr) {
    asm volatile("ldmatrix.sync.aligned.m8n8.x4.shared.b16 {%0,%1,%2,%3}, [%4];"
                 : "=r"(r[0]), "=r"(r[1]), "=r"(r[2]), "=r"(r[3]) : "r"(addr));
}
__device__ __forceinline__ void ldsm_x4_t(uint32_t* r, uint32_t addr) {
    asm volatile("ldmatrix.sync.aligned.m8n8.x4.trans.shared.b16 {%0,%1,%2,%3}, [%4];"
                 : "=r"(r[0]), "=r"(r[1]), "=r"(r[2]), "=r"(r[3]) : "r"(addr));
}

// fp32 -> fp16 (rn)
__global__ __launch_bounds__(256)
void cvt_f16_kernel(const float* __restrict__ in, __half* __restrict__ out)
{
    size_t i = ((size_t)blockIdx.x * 256 + threadIdx.x) * 4;
    float4 v = *(const float4*)(in + i);
    *(__half2*)(out + i)     = __floats2half2_rn(v.x, v.y);
    *(__half2*)(out + i + 2) = __floats2half2_rn(v.z, v.w);
}

// ===========================================================================
// Generic per-head projection on fp16 tensor cores
// ===========================================================================
#define KP_STG 4
#define KPA_STR 40
#define KPB_STR 136
#define KPA_H (128 * KPA_STR)
#define KPB_H (32 * KPB_STR)
#define KPSMEM (KP_STG * (KPA_H + KPB_H) * 2)   // 75776 B

__global__ void __launch_bounds__(256, 2)
proj_f16_kernel(const __half* __restrict__ A, const __half* __restrict__ W,
                const float* __restrict__ bias, __half* __restrict__ out,
                int Kdim, int Mtot)
{
    extern __shared__ __half kps[];
    const uint32_t sA = (uint32_t)__cvta_generic_to_shared(kps);
    const uint32_t sB = sA + KP_STG * KPA_H * 2;

    const int tid  = threadIdx.x;
    const int lane = tid & 31;
    const int wid  = tid >> 5;
    const int wm   = wid >> 2;
    const int wn   = wid & 3;
    const int z    = blockIdx.z;
    const int m0   = blockIdx.y * 128;

    const __half* Ap = A + (size_t)m0 * Kdim;
    const __half* Bp = W + (size_t)z * Kdim * DHEAD;

    const int a_r = tid >> 1;
    const int a_c = (tid & 1) << 4;
    const int b_r = tid >> 3;
    const int b_c = (tid & 7) << 4;

    float acc[4][4][4];
#pragma unroll
    for (int mt = 0; mt < 4; mt++)
#pragma unroll
        for (int nt = 0; nt < 4; nt++)
#pragma unroll
            for (int r = 0; r < 4; r++) acc[mt][nt][r] = 0.f;

    const int NT = Kdim / 32;

    auto issue = [&](int kt, int s) {
#pragma unroll
        for (int i = 0; i < 2; i++)
            cp_async16(sA + (uint32_t)(s * KPA_H + a_r * KPA_STR + a_c + 8 * i) * 2,
                       Ap + (size_t)a_r * Kdim + kt * 32 + a_c + 8 * i);
#pragma unroll
        for (int i = 0; i < 2; i++)
            cp_async16(sB + (uint32_t)(s * KPB_H + b_r * KPB_STR + b_c + 8 * i) * 2,
                       Bp + (size_t)(kt * 32 + b_r) * DHEAD + b_c + 8 * i);
        asm volatile("cp.async.commit_group;" ::: "memory");
    };

    issue(0, 0); issue(1, 1); issue(2, 2);

    int scur = 0;
    for (int kt = 0; kt < NT; kt++) {
        if (kt < NT - 2)       asm volatile("cp.async.wait_group 2;" ::: "memory");
        else if (kt == NT - 2) asm volatile("cp.async.wait_group 1;" ::: "memory");
        else                   asm volatile("cp.async.wait_group 0;" ::: "memory");
        __syncthreads();

        if (kt + 3 < NT) {
            int snx = scur + 3; if (snx >= KP_STG) snx -= KP_STG;
            issue(kt + 3, snx);
        }

        const uint32_t aB = sA + (uint32_t)(scur * KPA_H) * 2;
        const uint32_t bB = sB + (uint32_t)(scur * KPB_H) * 2;

#pragma unroll
        for (int ks = 0; ks < 2; ks++) {
            uint32_t bf[4][2];
#pragma unroll
            for (int ntp = 0; ntp < 2; ntp++) {
                uint32_t r[4];
                uint32_t addr = bB + (uint32_t)(((ks * 16 + (lane & 15)) * KPB_STR
                               + wn * 32 + ntp * 16 + ((lane >> 4) << 3)) * 2);
                ldsm_x4_t(r, addr);
                bf[2 * ntp][0]     = r[0];
                bf[2 * ntp][1]     = r[1];
                bf[2 * ntp + 1][0] = r[2];
                bf[2 * ntp + 1][1] = r[3];
            }
#pragma unroll
            for (int mt = 0; mt < 4; mt++) {
                uint32_t af[4];
                uint32_t addr = aB + (uint32_t)(((wm * 64 + mt * 16 + (lane & 15)) * KPA_STR
                               + ks * 16 + ((lane >> 4) << 3)) * 2);
                ldsm_x4(af, addr);
#pragma unroll
                for (int nt = 0; nt < 4; nt++)
                    mma_f16(acc[mt][nt], af, bf[nt]);
            }
        }
        scur++; if (scur >= KP_STG) scur -= KP_STG;
        __syncthreads();
    }

    __half* Op = out + (size_t)z * Mtot * DHEAD;
#pragma unroll
    for (int mt = 0; mt < 4; mt++) {
        const int r = m0 + wm * 64 + mt * 16 + (lane >> 2);
#pragma unroll
        for (int nt = 0; nt < 4; nt++) {
            const int c = wn * 32 + nt * 8 + ((lane & 3) << 1);
            float b0 = bias[z * DHEAD + c], b1 = bias[z * DHEAD + c + 1];
            *(__half2*)(Op + (size_t)r * DHEAD + c) =
                __floats2half2_rn(acc[mt][nt][0] + b0, acc[mt][nt][1] + b1);
            *(__half2*)(Op + (size_t)(r + 8) * DHEAD + c) =
                __floats2half2_rn(acc[mt][nt][2] + b0, acc[mt][nt][3] + b1);
        }
    }
}

// ===========================================================================
// Scores (per-head z param), CTA tile 128m x 256n, 512 thr (16 warps 4x4)
// ===========================================================================
#define SC_STR 136
#define SC_SMEM ((128 + 256) * SC_STR * 2)   // 104448 B dynamic

__global__ void __launch_bounds__(512, 1)
scores_f16_kernel(float scale, int z)
{
    extern __shared__ __half scs[];
    const uint32_t sA = (uint32_t)__cvta_generic_to_shared(scs);
    const uint32_t sB = sA + 128 * SC_STR * 2;
    __shared__ float red[32][256];

    const int tid  = threadIdx.x;
    const int lane = tid & 31;
    const int wid  = tid >> 5;
    const int wm   = wid >> 2;
    const int wn   = wid & 3;
    const int m0   = blockIdx.y * 128;
    const int n0   = blockIdx.x * 256;

    const __half* Ap = g_Sh + (size_t)z * NSENT * DHEAD + (size_t)m0 * DHEAD;
    const __half* Bp = g_Kh + (size_t)z * NKNOW * DHEAD + (size_t)n0 * DHEAD;

    {
        const int ra  = tid >> 2;
        const int ca  = (tid & 3) << 5;
#pragma unroll
        for (int i = 0; i < 4; i++)
            cp_async16(sA + (uint32_t)(ra * SC_STR + ca + 8 * i) * 2,
                       Ap + (size_t)ra * DHEAD + ca + 8 * i);
        const int rb  = tid >> 1;
        const int cb  = (tid & 1) << 6;
#pragma unroll
        for (int i = 0; i < 8; i++)
            cp_async16(sB + (uint32_t)(rb * SC_STR + cb + 8 * i) * 2,
                       Bp + (size_t)rb * DHEAD + cb + 8 * i);
        asm volatile("cp.async.commit_group;" ::: "memory");
        asm volatile("cp.async.wait_group 0;" ::: "memory");
        __syncthreads();
    }

    float acc[2][8][4];
#pragma unroll
    for (int mt = 0; mt < 2; mt++)
#pragma unroll
        for (int nt = 0; nt < 8; nt++)
#pragma unroll
            for (int r = 0; r < 4; r++) acc[mt][nt][r] = 0.f;

#pragma unroll
    for (int ks = 0; ks < 8; ks++) {
        uint32_t bf[8][2];
#pragma unroll
        for (int ntp = 0; ntp < 4; ntp++) {
            uint32_t r[4];
            uint32_t addr = sB + (uint32_t)(((wn * 64 + ntp * 16 + (lane & 15)) * SC_STR
                           + ks * 16 + ((lane >> 4) << 3)) * 2);
            ldsm_x4(r, addr);
            bf[2 * ntp][0]     = r[0];
            bf[2 * ntp][1]     = r[2];
            bf[2 * ntp + 1][0] = r[1];
            bf[2 * ntp + 1][1] = r[3];
        }
#pragma unroll
        for (int mt = 0; mt < 2; mt++) {
            uint32_t af[4];
            uint32_t addr = sA + (uint32_t)(((wm * 32 + mt * 16 + (lane & 15)) * SC_STR
                           + ks * 16 + ((lane >> 4) << 3)) * 2);
            ldsm_x4(af, addr);
#pragma unroll
            for (int nt = 0; nt < 8; nt++)
                mma_f16(acc[mt][nt], af, bf[nt]);
        }
    }

    float cp[16];
#pragma unroll
    for (int j = 0; j < 16; j++) cp[j] = 0.f;
    __half* Ep = g_Ah + (size_t)z * NSENT * NKNOW;
#pragma unroll
    for (int mt = 0; mt < 2; mt++) {
        const int r = m0 + wm * 32 + mt * 16 + (lane >> 2);
#pragma unroll
        for (int nt = 0; nt < 8; nt++) {
            const int c = n0 + wn * 64 + nt * 8 + ((lane & 3) << 1);
            float e0 = __expf(acc[mt][nt][0] * scale);
            float e1 = __expf(acc[mt][nt][1] * scale);
            float e2 = __expf(acc[mt][nt][2] * scale);
            float e3 = __expf(acc[mt][nt][3] * scale);
            *(__half2*)(Ep + (size_t)r * NKNOW + c)       = __floats2half2_rn(e0, e1);
            *(__half2*)(Ep + (size_t)(r + 8) * NKNOW + c) = __floats2half2_rn(e2, e3);
            cp[nt * 2]     += e0 + e2;
            cp[nt * 2 + 1] += e1 + e3;
        }
    }
    const int rr = wm * 8 + (lane >> 2);
#pragma unroll
    for (int nt = 0; nt < 8; nt++) {
        red[rr][wn * 64 + nt * 8 + ((lane & 3) << 1)]     = cp[nt * 2];
        red[rr][wn * 64 + nt * 8 + ((lane & 3) << 1) + 1] = cp[nt * 2 + 1];
    }
    __syncthreads();
    if (tid < 256) {
        float s = 0.f;
#pragma unroll
        for (int r = 0; r < 32; r++) s += red[r][tid];
        atomicAdd(&g_colsum[(size_t)z * NKNOW + n0 + tid], s);
    }
}

// ===========================================================================
// normalize_a (per-head): g_An = f16( e * 1/colsum )
// ===========================================================================
__global__ __launch_bounds__(256)
void normalize_a_kernel(int h)
{
    const int m = (blockIdx.x * 256 + threadIdx.x) * 2;
    const int n0 = blockIdx.y * 64;
    float2 cs = *(const float2*)&g_colsum[(size_t)h * NKNOW + m];
    const float iv0 = 1.f / cs.x, iv1 = 1.f / cs.y;
    const size_t base = (size_t)h * NSENT * NKNOW + (size_t)n0 * NKNOW + m;
    const __half* pe = g_Ah + base;
    __half*       pn = g_An + base;
#pragma unroll 4
    for (int nn = 0; nn < 64; nn++) {
        size_t idx = (size_t)nn * NKNOW;
        __half2 e = *(const __half2*)(pe + idx);
        *(__half2*)(pn + idx) = __floats2half2_rn(__half2float(__low2half(e))  * iv0,
                                                  __half2float(__high2half(e)) * iv1);
    }
}

// ===========================================================================
// normalize_b (per-head): attn fp32 = e * 1/colsum
// ===========================================================================
__global__ __launch_bounds__(256)
void normalize_b_kernel(float* __restrict__ attn, int h)
{
    const int m = (blockIdx.x * 256 + threadIdx.x) * 2;
    const int n0 = blockIdx.y * 64;
    float2 cs = *(const float2*)&g_colsum[(size_t)h * NKNOW + m];
    const float iv0 = 1.f / cs.x, iv1 = 1.f / cs.y;
    const size_t base = (size_t)h * NSENT * NKNOW + (size_t)n0 * NKNOW + m;
    const __half* pe = g_Ah + base;
    float*        p  = attn + base;
#pragma unroll 4
    for (int nn = 0; nn < 64; nn++) {
        size_t idx = (size_t)nn * NKNOW;
        __half2 e = *(const __half2*)(pe + idx);
        *(float2*)(p + idx) = make_float2(__half2float(__low2half(e))  * iv0,
                                          __half2float(__high2half(e)) * iv1);
    }
}

// ===========================================================================
// fused = attn_norm_h16 @ knowledge_h16 — SINGLE launch over all heads
//   R9 config: CTA 128x256xK64, 512 thr (16 warps 4x4), 3-stage cp.async
// ===========================================================================
#define FBM 128
#define FBN 256
#define FBK 64
#define FSTG 3
#define SA_STR 72
#define SB_STR 264
#define SA_H (FBM * SA_STR)
#define SB_H (FBK * SB_STR)
#define FSMEM (FSTG * (SA_H + SB_H) * 2)    // 156672 B

__global__ void __launch_bounds__(512, 1)
fused_mma_f16(float* __restrict__ C)
{
    extern __shared__ __half smh[];
    const uint32_t sA_u32 = (uint32_t)__cvta_generic_to_shared(smh);
    const uint32_t sB_u32 = sA_u32 + FSTG * SA_H * 2;

    const int tid  = threadIdx.x;
    const int lane = tid & 31;
    const int wid  = tid >> 5;
    const int wm   = wid & 3;
    const int wn   = wid >> 2;
    const int z    = blockIdx.z;
    const int m0   = blockIdx.y * FBM;
    const int n0   = blockIdx.x * FBN;

    const __half* Ap = g_An + (size_t)z * NSENT * NKNOW + (size_t)m0 * NKNOW;
    const __half* Bp = g_Bh + n0;

    const int a_row  = tid >> 2;
    const int a_ch   = (tid & 3) << 3;
    const int b_row0 = tid >> 5;
    const int b_ch0  = (tid & 31) << 3;

    float acc[2][8][4];
#pragma unroll
    for (int mt = 0; mt < 2; mt++)
#pragma unroll
        for (int nt = 0; nt < 8; nt++)
#pragma unroll
            for (int r = 0; r < 4; r++) acc[mt][nt][r] = 0.f;

    const int NT = NKNOW / FBK;             // 128

    auto issue = [&](int kt, int s) {
        const __half* abase = Ap + (size_t)kt * FBK;
#pragma unroll
        for (int i = 0; i < 2; i++)
            cp_async16(sA_u32 + (uint32_t)(s * SA_H + a_row * SA_STR + a_ch + 32 * i) * 2,
                       abase + (size_t)a_row * NKNOW + a_ch + 32 * i);
        const __half* bbase = Bp + (size_t)(kt * FBK) * KFDIM;
#pragma unroll
        for (int p = 0; p < 4; p++) {
            int row = b_row0 + p * 16;
            cp_async16(sB_u32 + (uint32_t)(s * SB_H + row * SB_STR + b_ch0) * 2,
                       bbase + (size_t)row * KFDIM + b_ch0);
        }
        asm volatile("cp.async.commit_group;" ::: "memory");
    };

    issue(0, 0); issue(1, 1);

    int scur = 0;
    for (int kt = 0; kt < NT; kt++) {
        if (kt + 1 < NT) asm volatile("cp.async.wait_group 1;" ::: "memory");
        else             asm volatile("cp.async.wait_group 0;" ::: "memory");
        __syncthreads();

        if (kt + 2 < NT) {
            int snx = scur + 2; if (snx >= FSTG) snx -= FSTG;
            issue(kt + 2, snx);
        }

        const uint32_t aBase = sA_u32 + (uint32_t)(scur * SA_H) * 2;
        const uint32_t bBase = sB_u32 + (uint32_t)(scur * SB_H) * 2;

#pragma unroll
        for (int ks = 0; ks < 4; ks++) {
            uint32_t bf[8][2];
#pragma unroll
            for (int ntp = 0; ntp < 4; ntp++) {
                uint32_t r[4];
                uint32_t addr = bBase + (uint32_t)(((ks * 16 + (lane & 15)) * SB_STR
                               + wn * 64 + ntp * 16 + ((lane >> 4) << 3)) * 2);
                ldsm_x4_t(r, addr);
                bf[2 * ntp][0]     = r[0];
                bf[2 * ntp][1]     = r[1];
                bf[2 * ntp + 1][0] = r[2];
                bf[2 * ntp + 1][1] = r[3];
            }
#pragma unroll
            for (int mt = 0; mt < 2; mt++) {
                uint32_t af[4];
                uint32_t addr = aBase + (uint32_t)(((wm * 32 + mt * 16 + (lane & 15)) * SA_STR
                               + ks * 16 + ((lane >> 4) << 3)) * 2);
                ldsm_x4(af, addr);
#pragma unroll
                for (int nt = 0; nt < 8; nt++)
                    mma_f16(acc[mt][nt], af, bf[nt]);
            }
        }
        scur++; if (scur >= FSTG) scur -= FSTG;
    }

    const int ldc = NHEADS * KFDIM;
#pragma unroll
    for (int mt = 0; mt < 2; mt++) {
        const int r = m0 + wm * 32 + mt * 16 + (lane >> 2);
#pragma unroll
        for (int nt = 0; nt < 8; nt++) {
            const int c = z * KFDIM + n0 + wn * 64 + nt * 8 + ((lane & 3) << 1);
            *(float2*)(C + (size_t)r * ldc + c)       = make_float2(acc[mt][nt][0], acc[mt][nt][1]);
            *(float2*)(C + (size_t)(r + 8) * ldc + c) = make_float2(acc[mt][nt][2], acc[mt][nt][3]);
        }
    }
}

// ===========================================================================
// Host side — per-head scores->norm_a pipelining; ONE fused launch
// ===========================================================================
extern "C" void kernel_launch(void* const* d_in, const int* in_sizes, int n_in,
                              void* d_out, int out_size)
{
    const float* sentences = (const float*)d_in[0];
    const float* knowledge = (const float*)d_in[1];
    const float* w_s       = (const float*)d_in[2];
    const float* b_s       = (const float*)d_in[3];
    const float* w_k       = (const float*)d_in[4];
    const float* b_k       = (const float*)d_in[5];

    float* attn  = (float*)d_out;
    float* fused = (float*)d_out + (size_t)NHEADS * NSENT * NKNOW;

    float* csum = nullptr;
    __half *snth = nullptr, *wsh = nullptr, *Sh = nullptr, *Kh = nullptr,
           *wkh = nullptr, *Bh = nullptr;
    cudaGetSymbolAddress((void**)&csum, g_colsum);
    cudaGetSymbolAddress((void**)&snth, g_snth);
    cudaGetSymbolAddress((void**)&wsh,  g_wsh);
    cudaGetSymbolAddress((void**)&Sh,   g_Sh);
    cudaGetSymbolAddress((void**)&Kh,   g_Kh);
    cudaGetSymbolAddress((void**)&wkh,  g_wkh);
    cudaGetSymbolAddress((void**)&Bh,   g_Bh);

    static cudaStream_t s2, s4;
    static cudaEvent_t evF0, evS, evSc[NHEADS], evNaAll, evJB;
    static bool init_done = false;
    if (!init_done) {
        cudaFuncSetAttribute(proj_f16_kernel,
                             cudaFuncAttributeMaxDynamicSharedMemorySize, KPSMEM);
        cudaFuncSetAttribute(scores_f16_kernel,
                             cudaFuncAttributeMaxDynamicSharedMemorySize, SC_SMEM);
        cudaFuncSetAttribute(fused_mma_f16,
                             cudaFuncAttributeMaxDynamicSharedMemorySize, FSMEM);
        cudaStreamCreateWithFlags(&s2, cudaStreamNonBlocking);
        cudaStreamCreateWithFlags(&s4, cudaStreamNonBlocking);
        cudaEventCreateWithFlags(&evF0,    cudaEventDisableTiming);
        cudaEventCreateWithFlags(&evS,     cudaEventDisableTiming);
        cudaEventCreateWithFlags(&evNaAll, cudaEventDisableTiming);
        cudaEventCreateWithFlags(&evJB,    cudaEventDisableTiming);
        for (int z = 0; z < NHEADS; z++)
            cudaEventCreateWithFlags(&evSc[z], cudaEventDisableTiming);
        init_done = true;
    }

    // 0) zero colsums; fork front-end
    cudaMemsetAsync(csum, 0, (size_t)NHEADS * NKNOW * sizeof(float));
    cudaEventRecord(evF0, 0);
    cudaStreamWaitEvent(s2, evF0, 0);

    // s2: sentences chain (cvt -> cvt -> sproj)
    cvt_f16_kernel<<<((size_t)NSENT * DMODEL) / 1024, 256, 0, s2>>>(sentences, snth);
    cvt_f16_kernel<<<((size_t)NHEADS * DMODEL * DHEAD) / 1024, 256, 0, s2>>>(w_s, wsh);
    {
        dim3 grid(1, NSENT / 128, NHEADS);
        proj_f16_kernel<<<grid, 256, KPSMEM, s2>>>(snth, wsh, b_s, Sh, DMODEL, NSENT);
    }
    cudaEventRecord(evS, s2);

    // main: knowledge chain (cvt -> cvt -> kproj)
    cvt_f16_kernel<<<((size_t)NKNOW * KFDIM) / 1024, 256>>>(knowledge, Bh);
    cvt_f16_kernel<<<((size_t)NHEADS * KFDIM * DHEAD) / 1024, 256>>>(w_k, wkh);
    {
        dim3 grid(1, NKNOW / 128, NHEADS);
        proj_f16_kernel<<<grid, 256, KPSMEM>>>(Bh, wkh, b_k, Kh, KFDIM, NKNOW);
    }
    cudaStreamWaitEvent((cudaStream_t)0, evS, 0);   // scores needs Sh + Kh

    // per-head scores on main; norm_a(z) on s2 + norm_b(z) on s4 chase them
    const dim3 gridSc(NKNOW / 256, NSENT / 128);
    const dim3 gridNm(NKNOW / 512, NSENT / 64);
    for (int z = 0; z < NHEADS; z++) {
        scores_f16_kernel<<<gridSc, 512, SC_SMEM>>>(0.08838834764831845f, z);
        cudaEventRecord(evSc[z], 0);
        cudaStreamWaitEvent(s2, evSc[z], 0);
        normalize_a_kernel<<<gridNm, 256, 0, s2>>>(z);
        cudaStreamWaitEvent(s4, evSc[z], 0);
        normalize_b_kernel<<<gridNm, 256, 0, s4>>>(attn, z);
    }
    cudaEventRecord(evNaAll, s2);
    cudaEventRecord(evJB, s4);

    // fused: ONE launch over all heads, after all norm_a
    cudaStreamWaitEvent((cudaStream_t)0, evNaAll, 0);
    {
        dim3 grid(KFDIM / FBN, NSENT / FBM, NHEADS);
        fused_mma_f16<<<grid, 512, FSMEM>>>(fused);
    }
    cudaStreamWaitEvent((cudaStream_t)0, evJB, 0);
}

// round 17
// speedup vs baseline: 1.3047x; 1.0037x over previous
#include <cuda_runtime.h>
#include <cuda_fp16.h>
#include <math.h>
#include <stdint.h>

#define NHEADS 8
#define DMODEL 1024
#define DHEAD  128
#define KFDIM  3072
#define NSENT  2048
#define NKNOW  8192

// Scratch (no cudaMalloc allowed).
__device__ __half g_snth[NSENT * DMODEL];               // 4 MB  sentences fp16
__device__ __half g_wsh[NHEADS * DMODEL * DHEAD];       // 2 MB  w_s fp16
__device__ __half g_Sh[NHEADS * NSENT * DHEAD];         // 4 MB  S fp16
__device__ __half g_Kh[NHEADS * NKNOW * DHEAD];         // 16 MB K fp16
__device__ __half g_wkh[NHEADS * KFDIM * DHEAD];        // 6 MB  w_k fp16
__device__ float  g_colsum[NHEADS * NKNOW];             // 256 KB
__device__ __half g_Ah[(size_t)NHEADS * NSENT * NKNOW]; // 268 MB e fp16
__device__ __half g_An[(size_t)NHEADS * NSENT * NKNOW]; // 268 MB normalized fp16
__device__ __half g_Bh[(size_t)NKNOW * KFDIM];          // 50 MB knowledge fp16

// ===========================================================================
// helpers
// ===========================================================================
__device__ __forceinline__ void mma_f16(float* d, const uint32_t* a, const uint32_t* b) {
    asm volatile(
        "mma.sync.aligned.m16n8k16.row.col.f32.f16.f16.f32 "
        "{%0,%1,%2,%3}, {%4,%5,%6,%7}, {%8,%9}, {%0,%1,%2,%3};"
        : "+f"(d[0]), "+f"(d[1]), "+f"(d[2]), "+f"(d[3])
        : "r"(a[0]), "r"(a[1]), "r"(a[2]), "r"(a[3]), "r"(b[0]), "r"(b[1]));
}
__device__ __forceinline__ void cp_async16(uint32_t dst, const void* src) {
    asm volatile("cp.async.cg.shared.global [%0], [%1], 16;" :: "r"(dst), "l"(src));
}
__device__ __forceinline__ void ldsm_x4(uint32_t* r, uint32_t addr) {
    asm volatile("ldmatrix.sync.aligned.m8n8.x4.shared.b16 {%0,%1,%2,%3}, [%4];"
                 : "=r"(r[0]), "=r"(r[1]), "=r"(r[2]), "=r"(r[3]) : "r"(addr));
}
__device__ __forceinline__ void ldsm_x4_t(uint32_t* r, uint32_t addr) {
    asm volatile("ldmatrix.sync.aligned.m8n8.x4.trans.shared.b16 {%0,%1,%2,%3}, [%4];"
                 : "=r"(r[0]), "=r"(r[1]), "=r"(r[2]), "=r"(r[3]) : "r"(addr));
}

// fp32 -> fp16 (rn)
__global__ __launch_bounds__(256)
void cvt_f16_kernel(const float* __restrict__ in, __half* __restrict__ out)
{
    size_t i = ((size_t)blockIdx.x * 256 + threadIdx.x) * 4;
    float4 v = *(const float4*)(in + i);
    *(__half2*)(out + i)     = __floats2half2_rn(v.x, v.y);
    *(__half2*)(out + i + 2) = __floats2half2_rn(v.z, v.w);
}

// ===========================================================================
// Generic per-head projection on fp16 tensor cores (zbase selects head range)
// ===========================================================================
#define KP_STG 4
#define KPA_STR 40
#define KPB_STR 136
#define KPA_H (128 * KPA_STR)
#define KPB_H (32 * KPB_STR)
#define KPSMEM (KP_STG * (KPA_H + KPB_H) * 2)   // 75776 B

__global__ void __launch_bounds__(256, 2)
proj_f16_kernel(const __half* __restrict__ A, const __half* __restrict__ W,
                const float* __restrict__ bias, __half* __restrict__ out,
                int Kdim, int Mtot, int zbase)
{
    extern __shared__ __half kps[];
    const uint32_t sA = (uint32_t)__cvta_generic_to_shared(kps);
    const uint32_t sB = sA + KP_STG * KPA_H * 2;

    const int tid  = threadIdx.x;
    const int lane = tid & 31;
    const int wid  = tid >> 5;
    const int wm   = wid >> 2;
    const int wn   = wid & 3;
    const int z    = zbase + blockIdx.z;
    const int m0   = blockIdx.y * 128;

    const __half* Ap = A + (size_t)m0 * Kdim;
    const __half* Bp = W + (size_t)z * Kdim * DHEAD;

    const int a_r = tid >> 1;
    const int a_c = (tid & 1) << 4;
    const int b_r = tid >> 3;
    const int b_c = (tid & 7) << 4;

    float acc[4][4][4];
#pragma unroll
    for (int mt = 0; mt < 4; mt++)
#pragma unroll
        for (int nt = 0; nt < 4; nt++)
#pragma unroll
            for (int r = 0; r < 4; r++) acc[mt][nt][r] = 0.f;

    const int NT = Kdim / 32;

    auto issue = [&](int kt, int s) {
#pragma unroll
        for (int i = 0; i < 2; i++)
            cp_async16(sA + (uint32_t)(s * KPA_H + a_r * KPA_STR + a_c + 8 * i) * 2,
                       Ap + (size_t)a_r * Kdim + kt * 32 + a_c + 8 * i);
#pragma unroll
        for (int i = 0; i < 2; i++)
            cp_async16(sB + (uint32_t)(s * KPB_H + b_r * KPB_STR + b_c + 8 * i) * 2,
                       Bp + (size_t)(kt * 32 + b_r) * DHEAD + b_c + 8 * i);
        asm volatile("cp.async.commit_group;" ::: "memory");
    };

    issue(0, 0); issue(1, 1); issue(2, 2);

    int scur = 0;
    for (int kt = 0; kt < NT; kt++) {
        if (kt < NT - 2)       asm volatile("cp.async.wait_group 2;" ::: "memory");
        else if (kt == NT - 2) asm volatile("cp.async.wait_group 1;" ::: "memory");
        else                   asm volatile("cp.async.wait_group 0;" ::: "memory");
        __syncthreads();

        if (kt + 3 < NT) {
            int snx = scur + 3; if (snx >= KP_STG) snx -= KP_STG;
            issue(kt + 3, snx);
        }

        const uint32_t aB = sA + (uint32_t)(scur * KPA_H) * 2;
        const uint32_t bB = sB + (uint32_t)(scur * KPB_H) * 2;

#pragma unroll
        for (int ks = 0; ks < 2; ks++) {
            uint32_t bf[4][2];
#pragma unroll
            for (int ntp = 0; ntp < 2; ntp++) {
                uint32_t r[4];
                uint32_t addr = bB + (uint32_t)(((ks * 16 + (lane & 15)) * KPB_STR
                               + wn * 32 + ntp * 16 + ((lane >> 4) << 3)) * 2);
                ldsm_x4_t(r, addr);
                bf[2 * ntp][0]     = r[0];
                bf[2 * ntp][1]     = r[1];
                bf[2 * ntp + 1][0] = r[2];
                bf[2 * ntp + 1][1] = r[3];
            }
#pragma unroll
            for (int mt = 0; mt < 4; mt++) {
                uint32_t af[4];
                uint32_t addr = aB + (uint32_t)(((wm * 64 + mt * 16 + (lane & 15)) * KPA_STR
                               + ks * 16 + ((lane >> 4) << 3)) * 2);
                ldsm_x4(af, addr);
#pragma unroll
                for (int nt = 0; nt < 4; nt++)
                    mma_f16(acc[mt][nt], af, bf[nt]);
            }
        }
        scur++; if (scur >= KP_STG) scur -= KP_STG;
        __syncthreads();
    }

    __half* Op = out + (size_t)z * Mtot * DHEAD;
#pragma unroll
    for (int mt = 0; mt < 4; mt++) {
        const int r = m0 + wm * 64 + mt * 16 + (lane >> 2);
#pragma unroll
        for (int nt = 0; nt < 4; nt++) {
            const int c = wn * 32 + nt * 8 + ((lane & 3) << 1);
            float b0 = bias[z * DHEAD + c], b1 = bias[z * DHEAD + c + 1];
            *(__half2*)(Op + (size_t)r * DHEAD + c) =
                __floats2half2_rn(acc[mt][nt][0] + b0, acc[mt][nt][1] + b1);
            *(__half2*)(Op + (size_t)(r + 8) * DHEAD + c) =
                __floats2half2_rn(acc[mt][nt][2] + b0, acc[mt][nt][3] + b1);
        }
    }
}

// ===========================================================================
// Scores (per-head z param), CTA tile 128m x 256n, 512 thr (16 warps 4x4)
// ===========================================================================
#define SC_STR 136
#define SC_SMEM ((128 + 256) * SC_STR * 2)   // 104448 B dynamic

__global__ void __launch_bounds__(512, 1)
scores_f16_kernel(float scale, int z)
{
    extern __shared__ __half scs[];
    const uint32_t sA = (uint32_t)__cvta_generic_to_shared(scs);
    const uint32_t sB = sA + 128 * SC_STR * 2;
    __shared__ float red[32][256];

    const int tid  = threadIdx.x;
    const int lane = tid & 31;
    const int wid  = tid >> 5;
    const int wm   = wid >> 2;
    const int wn   = wid & 3;
    const int m0   = blockIdx.y * 128;
    const int n0   = blockIdx.x * 256;

    const __half* Ap = g_Sh + (size_t)z * NSENT * DHEAD + (size_t)m0 * DHEAD;
    const __half* Bp = g_Kh + (size_t)z * NKNOW * DHEAD + (size_t)n0 * DHEAD;

    {
        const int ra  = tid >> 2;
        const int ca  = (tid & 3) << 5;
#pragma unroll
        for (int i = 0; i < 4; i++)
            cp_async16(sA + (uint32_t)(ra * SC_STR + ca + 8 * i) * 2,
                       Ap + (size_t)ra * DHEAD + ca + 8 * i);
        const int rb  = tid >> 1;
        const int cb  = (tid & 1) << 6;
#pragma unroll
        for (int i = 0; i < 8; i++)
            cp_async16(sB + (uint32_t)(rb * SC_STR + cb + 8 * i) * 2,
                       Bp + (size_t)rb * DHEAD + cb + 8 * i);
        asm volatile("cp.async.commit_group;" ::: "memory");
        asm volatile("cp.async.wait_group 0;" ::: "memory");
        __syncthreads();
    }

    float acc[2][8][4];
#pragma unroll
    for (int mt = 0; mt < 2; mt++)
#pragma unroll
        for (int nt = 0; nt < 8; nt++)
#pragma unroll
            for (int r = 0; r < 4; r++) acc[mt][nt][r] = 0.f;

#pragma unroll
    for (int ks = 0; ks < 8; ks++) {
        uint32_t bf[8][2];
#pragma unroll
        for (int ntp = 0; ntp < 4; ntp++) {
            uint32_t r[4];
            uint32_t addr = sB + (uint32_t)(((wn * 64 + ntp * 16 + (lane & 15)) * SC_STR
                           + ks * 16 + ((lane >> 4) << 3)) * 2);
            ldsm_x4(r, addr);
            bf[2 * ntp][0]     = r[0];
            bf[2 * ntp][1]     = r[2];
            bf[2 * ntp + 1][0] = r[1];
            bf[2 * ntp + 1][1] = r[3];
        }
#pragma unroll
        for (int mt = 0; mt < 2; mt++) {
            uint32_t af[4];
            uint32_t addr = sA + (uint32_t)(((wm * 32 + mt * 16 + (lane & 15)) * SC_STR
                           + ks * 16 + ((lane >> 4) << 3)) * 2);
            ldsm_x4(af, addr);
#pragma unroll
            for (int nt = 0; nt < 8; nt++)
                mma_f16(acc[mt][nt], af, bf[nt]);
        }
    }

    float cp[16];
#pragma unroll
    for (int j = 0; j < 16; j++) cp[j] = 0.f;
    __half* Ep = g_Ah + (size_t)z * NSENT * NKNOW;
#pragma unroll
    for (int mt = 0; mt < 2; mt++) {
        const int r = m0 + wm * 32 + mt * 16 + (lane >> 2);
#pragma unroll
        for (int nt = 0; nt < 8; nt++) {
            const int c = n0 + wn * 64 + nt * 8 + ((lane & 3) << 1);
            float e0 = __expf(acc[mt][nt][0] * scale);
            float e1 = __expf(acc[mt][nt][1] * scale);
            float e2 = __expf(acc[mt][nt][2] * scale);
            float e3 = __expf(acc[mt][nt][3] * scale);
            *(__half2*)(Ep + (size_t)r * NKNOW + c)       = __floats2half2_rn(e0, e1);
            *(__half2*)(Ep + (size_t)(r + 8) * NKNOW + c) = __floats2half2_rn(e2, e3);
            cp[nt * 2]     += e0 + e2;
            cp[nt * 2 + 1] += e1 + e3;
        }
    }
    const int rr = wm * 8 + (lane >> 2);
#pragma unroll
    for (int nt = 0; nt < 8; nt++) {
        red[rr][wn * 64 + nt * 8 + ((lane & 3) << 1)]     = cp[nt * 2];
        red[rr][wn * 64 + nt * 8 + ((lane & 3) << 1) + 1] = cp[nt * 2 + 1];
    }
    __syncthreads();
    if (tid < 256) {
        float s = 0.f;
#pragma unroll
        for (int r = 0; r < 32; r++) s += red[r][tid];
        atomicAdd(&g_colsum[(size_t)z * NKNOW + n0 + tid], s);
    }
}

// ===========================================================================
// normalize_a (per-head): g_An = f16( e * 1/colsum )
// ===========================================================================
__global__ __launch_bounds__(256)
void normalize_a_kernel(int h)
{
    const int m = (blockIdx.x * 256 + threadIdx.x) * 2;
    const int n0 = blockIdx.y * 64;
    float2 cs = *(const float2*)&g_colsum[(size_t)h * NKNOW + m];
    const float iv0 = 1.f / cs.x, iv1 = 1.f / cs.y;
    const size_t base = (size_t)h * NSENT * NKNOW + (size_t)n0 * NKNOW + m;
    const __half* pe = g_Ah + base;
    __half*       pn = g_An + base;
#pragma unroll 4
    for (int nn = 0; nn < 64; nn++) {
        size_t idx = (size_t)nn * NKNOW;
        __half2 e = *(const __half2*)(pe + idx);
        *(__half2*)(pn + idx) = __floats2half2_rn(__half2float(__low2half(e))  * iv0,
                                                  __half2float(__high2half(e)) * iv1);
    }
}

// ===========================================================================
// normalize_b (per-head): attn fp32 = e * 1/colsum
// ===========================================================================
__global__ __launch_bounds__(256)
void normalize_b_kernel(float* __restrict__ attn, int h)
{
    const int m = (blockIdx.x * 256 + threadIdx.x) * 2;
    const int n0 = blockIdx.y * 64;
    float2 cs = *(const float2*)&g_colsum[(size_t)h * NKNOW + m];
    const float iv0 = 1.f / cs.x, iv1 = 1.f / cs.y;
    const size_t base = (size_t)h * NSENT * NKNOW + (size_t)n0 * NKNOW + m;
    const __half* pe = g_Ah + base;
    float*        p  = attn + base;
#pragma unroll 4
    for (int nn = 0; nn < 64; nn++) {
        size_t idx = (size_t)nn * NKNOW;
        __half2 e = *(const __half2*)(pe + idx);
        *(float2*)(p + idx) = make_float2(__half2float(__low2half(e))  * iv0,
                                          __half2float(__high2half(e)) * iv1);
    }
}

// ===========================================================================
// fused = attn_norm_h16 @ knowledge_h16 — SINGLE launch over all heads
//   R9 config: CTA 128x256xK64, 512 thr (16 warps 4x4), 3-stage cp.async
// ===========================================================================
#define FBM 128
#define FBN 256
#define FBK 64
#define FSTG 3
#define SA_STR 72
#define SB_STR 264
#define SA_H (FBM * SA_STR)
#define SB_H (FBK * SB_STR)
#define FSMEM (FSTG * (SA_H + SB_H) * 2)    // 156672 B

__global__ void __launch_bounds__(512, 1)
fused_mma_f16(float* __restrict__ C)
{
    extern __shared__ __half smh[];
    const uint32_t sA_u32 = (uint32_t)__cvta_generic_to_shared(smh);
    const uint32_t sB_u32 = sA_u32 + FSTG * SA_H * 2;

    const int tid  = threadIdx.x;
    const int lane = tid & 31;
    const int wid  = tid >> 5;
    const int wm   = wid & 3;
    const int wn   = wid >> 2;
    const int z    = blockIdx.z;
    const int m0   = blockIdx.y * FBM;
    const int n0   = blockIdx.x * FBN;

    const __half* Ap = g_An + (size_t)z * NSENT * NKNOW + (size_t)m0 * NKNOW;
    const __half* Bp = g_Bh + n0;

    const int a_row  = tid >> 2;
    const int a_ch   = (tid & 3) << 3;
    const int b_row0 = tid >> 5;
    const int b_ch0  = (tid & 31) << 3;

    float acc[2][8][4];
#pragma unroll
    for (int mt = 0; mt < 2; mt++)
#pragma unroll
        for (int nt = 0; nt < 8; nt++)
#pragma unroll
            for (int r = 0; r < 4; r++) acc[mt][nt][r] = 0.f;

    const int NT = NKNOW / FBK;             // 128

    auto issue = [&](int kt, int s) {
        const __half* abase = Ap + (size_t)kt * FBK;
#pragma unroll
        for (int i = 0; i < 2; i++)
            cp_async16(sA_u32 + (uint32_t)(s * SA_H + a_row * SA_STR + a_ch + 32 * i) * 2,
                       abase + (size_t)a_row * NKNOW + a_ch + 32 * i);
        const __half* bbase = Bp + (size_t)(kt * FBK) * KFDIM;
#pragma unroll
        for (int p = 0; p < 4; p++) {
            int row = b_row0 + p * 16;
            cp_async16(sB_u32 + (uint32_t)(s * SB_H + row * SB_STR + b_ch0) * 2,
                       bbase + (size_t)row * KFDIM + b_ch0);
        }
        asm volatile("cp.async.commit_group;" ::: "memory");
    };

    issue(0, 0); issue(1, 1);

    int scur = 0;
    for (int kt = 0; kt < NT; kt++) {
        if (kt + 1 < NT) asm volatile("cp.async.wait_group 1;" ::: "memory");
        else             asm volatile("cp.async.wait_group 0;" ::: "memory");
        __syncthreads();

        if (kt + 2 < NT) {
            int snx = scur + 2; if (snx >= FSTG) snx -= FSTG;
            issue(kt + 2, snx);
        }

        const uint32_t aBase = sA_u32 + (uint32_t)(scur * SA_H) * 2;
        const uint32_t bBase = sB_u32 + (uint32_t)(scur * SB_H) * 2;

#pragma unroll
        for (int ks = 0; ks < 4; ks++) {
            uint32_t bf[8][2];
#pragma unroll
            for (int ntp = 0; ntp < 4; ntp++) {
                uint32_t r[4];
                uint32_t addr = bBase + (uint32_t)(((ks * 16 + (lane & 15)) * SB_STR
                               + wn * 64 + ntp * 16 + ((lane >> 4) << 3)) * 2);
                ldsm_x4_t(r, addr);
                bf[2 * ntp][0]     = r[0];
                bf[2 * ntp][1]     = r[1];
                bf[2 * ntp + 1][0] = r[2];
                bf[2 * ntp + 1][1] = r[3];
            }
#pragma unroll
            for (int mt = 0; mt < 2; mt++) {
                uint32_t af[4];
                uint32_t addr = aBase + (uint32_t)(((wm * 32 + mt * 16 + (lane & 15)) * SA_STR
                               + ks * 16 + ((lane >> 4) << 3)) * 2);
                ldsm_x4(af, addr);
#pragma unroll
                for (int nt = 0; nt < 8; nt++)
                    mma_f16(acc[mt][nt], af, bf[nt]);
            }
        }
        scur++; if (scur >= FSTG) scur -= FSTG;
    }

    const int ldc = NHEADS * KFDIM;
#pragma unroll
    for (int mt = 0; mt < 2; mt++) {
        const int r = m0 + wm * 32 + mt * 16 + (lane >> 2);
#pragma unroll
        for (int nt = 0; nt < 8; nt++) {
            const int c = z * KFDIM + n0 + wn * 64 + nt * 8 + ((lane & 3) << 1);
            *(float2*)(C + (size_t)r * ldc + c)       = make_float2(acc[mt][nt][0], acc[mt][nt][1]);
            *(float2*)(C + (size_t)(r + 8) * ldc + c) = make_float2(acc[mt][nt][2], acc[mt][nt][3]);
        }
    }
}

// ===========================================================================
// Host side — split kproj halves; per-head scores->norm chase; ONE fused
// ===========================================================================
extern "C" void kernel_launch(void* const* d_in, const int* in_sizes, int n_in,
                              void* d_out, int out_size)
{
    const float* sentences = (const float*)d_in[0];
    const float* knowledge = (const float*)d_in[1];
    const float* w_s       = (const float*)d_in[2];
    const float* b_s       = (const float*)d_in[3];
    const float* w_k       = (const float*)d_in[4];
    const float* b_k       = (const float*)d_in[5];

    float* attn  = (float*)d_out;
    float* fused = (float*)d_out + (size_t)NHEADS * NSENT * NKNOW;

    float* csum = nullptr;
    __half *snth = nullptr, *wsh = nullptr, *Sh = nullptr, *Kh = nullptr,
           *wkh = nullptr, *Bh = nullptr;
    cudaGetSymbolAddress((void**)&csum, g_colsum);
    cudaGetSymbolAddress((void**)&snth, g_snth);
    cudaGetSymbolAddress((void**)&wsh,  g_wsh);
    cudaGetSymbolAddress((void**)&Sh,   g_Sh);
    cudaGetSymbolAddress((void**)&Kh,   g_Kh);
    cudaGetSymbolAddress((void**)&wkh,  g_wkh);
    cudaGetSymbolAddress((void**)&Bh,   g_Bh);

    static cudaStream_t s2, s4, s5;
    static cudaEvent_t evF0, evS, evCvt, evKB, evSc[NHEADS], evNaAll, evJB;
    static bool init_done = false;
    if (!init_done) {
        cudaFuncSetAttribute(proj_f16_kernel,
                             cudaFuncAttributeMaxDynamicSharedMemorySize, KPSMEM);
        cudaFuncSetAttribute(scores_f16_kernel,
                             cudaFuncAttributeMaxDynamicSharedMemorySize, SC_SMEM);
        cudaFuncSetAttribute(fused_mma_f16,
                             cudaFuncAttributeMaxDynamicSharedMemorySize, FSMEM);
        cudaStreamCreateWithFlags(&s2, cudaStreamNonBlocking);
        cudaStreamCreateWithFlags(&s4, cudaStreamNonBlocking);
        cudaStreamCreateWithFlags(&s5, cudaStreamNonBlocking);
        cudaEventCreateWithFlags(&evF0,    cudaEventDisableTiming);
        cudaEventCreateWithFlags(&evS,     cudaEventDisableTiming);
        cudaEventCreateWithFlags(&evCvt,   cudaEventDisableTiming);
        cudaEventCreateWithFlags(&evKB,    cudaEventDisableTiming);
        cudaEventCreateWithFlags(&evNaAll, cudaEventDisableTiming);
        cudaEventCreateWithFlags(&evJB,    cudaEventDisableTiming);
        for (int z = 0; z < NHEADS; z++)
            cudaEventCreateWithFlags(&evSc[z], cudaEventDisableTiming);
        init_done = true;
    }

    // 0) zero colsums; fork sentence chain
    cudaMemsetAsync(csum, 0, (size_t)NHEADS * NKNOW * sizeof(float));
    cudaEventRecord(evF0, 0);
    cudaStreamWaitEvent(s2, evF0, 0);

    // s2: sentences chain (cvt -> cvt -> sproj heads 0..7)
    cvt_f16_kernel<<<((size_t)NSENT * DMODEL) / 1024, 256, 0, s2>>>(sentences, snth);
    cvt_f16_kernel<<<((size_t)NHEADS * DMODEL * DHEAD) / 1024, 256, 0, s2>>>(w_s, wsh);
    {
        dim3 grid(1, NSENT / 128, NHEADS);
        proj_f16_kernel<<<grid, 256, KPSMEM, s2>>>(snth, wsh, b_s, Sh, DMODEL, NSENT, 0);
    }
    cudaEventRecord(evS, s2);

    // main: knowledge cvts, then kproj heads 0..3; heads 4..7 on s5 concurrently
    cvt_f16_kernel<<<((size_t)NKNOW * KFDIM) / 1024, 256>>>(knowledge, Bh);
    cvt_f16_kernel<<<((size_t)NHEADS * KFDIM * DHEAD) / 1024, 256>>>(w_k, wkh);
    cudaEventRecord(evCvt, 0);
    cudaStreamWaitEvent(s5, evCvt, 0);
    {
        dim3 gridB(1, NKNOW / 128, NHEADS / 2);
        proj_f16_kernel<<<gridB, 256, KPSMEM, s5>>>(Bh, wkh, b_k, Kh, KFDIM, NKNOW, NHEADS / 2);
    }
    cudaEventRecord(evKB, s5);
    {
        dim3 gridA(1, NKNOW / 128, NHEADS / 2);
        proj_f16_kernel<<<gridA, 256, KPSMEM>>>(Bh, wkh, b_k, Kh, KFDIM, NKNOW, 0);
    }
    cudaStreamWaitEvent((cudaStream_t)0, evS, 0);   // scores needs Sh

    // per-head scores (heads 4..7 additionally gate on kproj-B);
    // norm_a(z) on s2 + norm_b(z) on s4 chase each head
    const dim3 gridSc(NKNOW / 256, NSENT / 128);
    const dim3 gridNm(NKNOW / 512, NSENT / 64);
    for (int z = 0; z < NHEADS; z++) {
        if (z == NHEADS / 2) cudaStreamWaitEvent((cudaStream_t)0, evKB, 0);
        scores_f16_kernel<<<gridSc, 512, SC_SMEM>>>(0.08838834764831845f, z);
        cudaEventRecord(evSc[z], 0);
        cudaStreamWaitEvent(s2, evSc[z], 0);
        normalize_a_kernel<<<gridNm, 256, 0, s2>>>(z);
        cudaStreamWaitEvent(s4, evSc[z], 0);
        normalize_b_kernel<<<gridNm, 256, 0, s4>>>(attn, z);
    }
    cudaEventRecord(evNaAll, s2);
    cudaEventRecord(evJB, s4);

    // fused: ONE launch over all heads, after all norm_a
    cudaStreamWaitEvent((cudaStream_t)0, evNaAll, 0);
    {
        dim3 grid(KFDIM / FBN, NSENT / FBM, NHEADS);
        fused_mma_f16<<<grid, 512, FSMEM>>>(fused);
    }
    cudaStreamWaitEvent((cudaStream_t)0, evJB, 0);
}